// round 5
// baseline (speedup 1.0000x reference)
#include <cuda_runtime.h>
#include <math.h>
#include <stdint.h>

#define N_NODES 100000
#define E_EDGES 400000
#define HID 128
#define HD 256

// ---------------- scratch ----------------
__device__ float    g_h[(size_t)N_NODES * HID];
__device__ float    g_q[(size_t)N_NODES * HD];
__device__ float    g_k[(size_t)N_NODES * HD];
__device__ float    g_v[(size_t)N_NODES * HD];
__device__ float    g_out[(size_t)N_NODES * HD];
__device__ unsigned g_smax[(size_t)N_NODES * 4];
__device__ float    g_denom[(size_t)N_NODES * 4];
__device__ float    g_e[(size_t)E_EDGES * 4];

__device__ __forceinline__ unsigned fenc(float f) {
    unsigned b = __float_as_uint(f);
    return (b & 0x80000000u) ? ~b : (b | 0x80000000u);
}
__device__ __forceinline__ float fdec(unsigned u) {
    unsigned b = (u & 0x80000000u) ? (u & 0x7fffffffu) : ~u;
    return __uint_as_float(b);
}

__device__ __forceinline__ float to_tf32(float v) {
    unsigned t;
    asm("cvt.rna.tf32.f32 %0, %1;" : "=r"(t) : "f"(v));
    return __uint_as_float(t);
}

__device__ __forceinline__ void mma_tf32(float* d, unsigned a0, unsigned a1, unsigned a2, unsigned a3,
                                         unsigned b0, unsigned b1) {
    asm volatile(
        "mma.sync.aligned.m16n8k8.row.col.f32.tf32.tf32.f32 "
        "{%0,%1,%2,%3}, {%4,%5,%6,%7}, {%8,%9}, {%0,%1,%2,%3};"
        : "+f"(d[0]), "+f"(d[1]), "+f"(d[2]), "+f"(d[3])
        : "r"(a0), "r"(a1), "r"(a2), "r"(a3), "r"(b0), "r"(b1));
}

// fragment-major addressing helpers
// A tile 16x8 (row r 0..15, col c 0..7): lane=(r&7)*4+(c&3), reg=(r>>3)+2*(c>>2)
// B tile 8x8  (k kk 0..7, col n 0..7):  lane=(n&7)*4+(kk&3), reg=kk>>2

// ---------------- small kernels ----------------
__global__ void init_kernel() {
    int i = blockIdx.x * blockDim.x + threadIdx.x;
    if (i < N_NODES * 4) { g_smax[i] = 0u; g_denom[i] = 0.f; }
}

__global__ void addh_kernel(const float4* __restrict__ x, const float4* __restrict__ mem) {
    int i = blockIdx.x * blockDim.x + threadIdx.x;
    if (i < N_NODES * HID / 4) {
        float4 a = x[i], b = mem[i];
        ((float4*)g_h)[i] = make_float4(a.x + b.x, a.y + b.y, a.z + b.z, a.w + b.w);
    }
}

// ---------------- node GEMM (tf32 mma): C = g_h @ W + b ----------------
// block 256 thr (8 warps), tile 128 rows x 64 cols, K=128 in 2 chunks of 64
__global__ void gemm_tf32_kernel(const float* __restrict__ W, const float* __restrict__ bias, int sel) {
    __shared__ float sA[8 * 8 * 32 * 4];   // 8 mt x 8 kt tiles, frag-major (32KB)
    __shared__ float sB[8 * 8 * 32 * 2];   // 8 kt x 8 nt tiles (16KB)
    float* C = (sel == 0) ? g_q : (sel == 1) ? g_k : (sel == 2) ? g_v : g_out;

    int row0 = blockIdx.x * 128;
    int col0 = blockIdx.y * 64;
    int tid = threadIdx.x;
    int wid = tid >> 5, lane = tid & 31;
    int g = lane >> 2, tig = lane & 3;
    float acc[8][4] = {};

    for (int ch = 0; ch < 2; ++ch) {
        int k0 = ch * 64;
#pragma unroll
        for (int i = 0; i < 32; i++) {          // A: 128 rows x 64 k
            int idx = tid + i * 256;
            int row = idx >> 6, k = idx & 63;
            int gr = row0 + row;
            float v = (gr < N_NODES) ? g_h[(size_t)gr * HID + k0 + k] : 0.f;
            int mt = row >> 4, r = row & 15, kt = k >> 3, c = k & 7;
            sA[(((mt * 8 + kt) * 32) + ((r & 7) * 4 + (c & 3))) * 4 + ((r >> 3) + 2 * (c >> 2))] = to_tf32(v);
        }
#pragma unroll
        for (int i = 0; i < 16; i++) {          // B: 64 k x 64 n
            int idx = tid + i * 256;
            int k = idx >> 6, n = idx & 63;
            float v = W[(size_t)(k0 + k) * HD + col0 + n];
            int kt = k >> 3, kk = k & 7, nt = n >> 3;
            sB[(((kt * 8 + nt) * 32) + ((n & 7) * 4 + (kk & 3))) * 2 + (kk >> 2)] = to_tf32(v);
        }
        __syncthreads();
#pragma unroll
        for (int kt = 0; kt < 8; ++kt) {
            float4 af = *(const float4*)&sA[((wid * 8 + kt) * 32 + lane) * 4];
            unsigned a0 = __float_as_uint(af.x), a1 = __float_as_uint(af.y);
            unsigned a2 = __float_as_uint(af.z), a3 = __float_as_uint(af.w);
#pragma unroll
            for (int nt = 0; nt < 8; ++nt) {
                float2 bf = *(const float2*)&sB[((kt * 8 + nt) * 32 + lane) * 2];
                mma_tf32(acc[nt], a0, a1, a2, a3, __float_as_uint(bf.x), __float_as_uint(bf.y));
            }
        }
        __syncthreads();
    }
    int gr0 = row0 + wid * 16 + g;
#pragma unroll
    for (int nt = 0; nt < 8; ++nt) {
        int gc = col0 + nt * 8 + 2 * tig;
        float bx = bias[gc], by = bias[gc + 1];
        if (gr0 < N_NODES)
            *(float2*)&C[(size_t)gr0 * HD + gc] = make_float2(acc[nt][0] + bx, acc[nt][1] + by);
        if (gr0 + 8 < N_NODES)
            *(float2*)&C[(size_t)(gr0 + 8) * HD + gc] = make_float2(acc[nt][2] + bx, acc[nt][3] + by);
    }
}

// ---------------- attention (unchanged) ----------------
__global__ void scores_kernel(const int* __restrict__ ei) {
    int w = (blockIdx.x * blockDim.x + threadIdx.x) >> 5;
    int lane = threadIdx.x & 31;
    if (w >= E_EDGES) return;
    int src = ei[w];
    int dst = ei[E_EDGES + w];
    const float* qd = g_q + (size_t)dst * HD;
    const float* ks = g_k + (size_t)src * HD;
#pragma unroll
    for (int h = 0; h < 4; ++h) {
        float p = qd[h * 64 + lane] * ks[h * 64 + lane]
                + qd[h * 64 + 32 + lane] * ks[h * 64 + 32 + lane];
#pragma unroll
        for (int o = 16; o > 0; o >>= 1) p += __shfl_xor_sync(0xffffffffu, p, o);
        p *= 0.125f;
        if (lane == 0) {
            g_e[(size_t)w * 4 + h] = p;
            atomicMax(&g_smax[(size_t)dst * 4 + h], fenc(p));
        }
    }
}

__global__ void expden_kernel(const int* __restrict__ ei) {
    int i = blockIdx.x * blockDim.x + threadIdx.x;
    if (i >= E_EDGES * 4) return;
    int e = i >> 2, h = i & 3;
    int dst = ei[E_EDGES + e];
    float m = fdec(g_smax[(size_t)dst * 4 + h]);
    float ex = expf(g_e[i] - m);
    g_e[i] = ex;
    atomicAdd(&g_denom[(size_t)dst * 4 + h], ex);
}

__global__ void agg_kernel(const int* __restrict__ ei) {
    int w = (blockIdx.x * blockDim.x + threadIdx.x) >> 5;
    int lane = threadIdx.x & 31;
    if (w >= E_EDGES) return;
    int src = ei[w];
    int dst = ei[E_EDGES + w];
    const float* vs = g_v + (size_t)src * HD;
    float* od = g_out + (size_t)dst * HD;
#pragma unroll
    for (int h = 0; h < 4; ++h) {
        float alpha = g_e[(size_t)w * 4 + h] / (g_denom[(size_t)dst * 4 + h] + 1e-16f);
        atomicAdd(&od[h * 64 + lane], alpha * vs[h * 64 + lane]);
        atomicAdd(&od[h * 64 + 32 + lane], alpha * vs[h * 64 + 32 + lane]);
    }
}

// ---------------- fused edge MLP (tf32 mma for layers 1,2) ----------------
// block: 256 thr (8 warps), 64 edges.
// L1: [64 x 512] @ [512 x 128] ; warp = (wm 0..3: 16 edges) x (wn 0..1: 64 cols)
// L2: [64 x 128] @ [128 x 64]  ; warp = (wm2 0..3) x (wn2 0..1: 32 cols)
// L3: fp32 dot(64) + sigmoid
__global__ void edge_mlp_kernel(const int* __restrict__ ei,
                                const float* __restrict__ W1, const float* __restrict__ b1,
                                const float* __restrict__ W2, const float* __restrict__ b2,
                                const float* __restrict__ W3, const float* __restrict__ b3,
                                float* __restrict__ out) {
    extern __shared__ float sm[];
    __shared__ int s_src[64], s_dst[64];

    int e0 = blockIdx.x * 64;
    int tid = threadIdx.x;
    int wid = tid >> 5, lane = tid & 31;
    int g = lane >> 2, tig = lane & 3;
    int wm = wid & 3, wn = wid >> 2;

    if (tid < 64) {
        s_src[tid] = ei[e0 + tid];
        s_dst[tid] = ei[E_EDGES + e0 + tid];
    }
    __syncthreads();

    // ---- layer 1 ----
    float* sA1 = sm;            // 4 mt x 8 kt x 32 x 4 = 4096 floats
    float* sB1 = sm + 4096;     // 8 kt x 16 nt x 32 x 2 = 8192 floats
    float acc[8][4] = {};

    for (int ch = 0; ch < 8; ++ch) {
        int k0 = ch * 64;
#pragma unroll
        for (int i = 0; i < 16; i++) {          // A: 64 edges x 64 k (gather)
            int idx = tid + i * 256;
            int e = idx >> 6, k = idx & 63;
            int col = k0 + k;
            float v = (col < HD) ? g_out[(size_t)s_src[e] * HD + col]
                                 : g_out[(size_t)s_dst[e] * HD + (col - HD)];
            int mt = e >> 4, r = e & 15, kt = k >> 3, c = k & 7;
            sA1[(((mt * 8 + kt) * 32) + ((r & 7) * 4 + (c & 3))) * 4 + ((r >> 3) + 2 * (c >> 2))] = to_tf32(v);
        }
#pragma unroll
        for (int i = 0; i < 32; i++) {          // B: 64 k x 128 n
            int idx = tid + i * 256;
            int k = idx >> 7, n = idx & 127;
            float v = W1[(size_t)(k0 + k) * 128 + n];
            int kt = k >> 3, kk = k & 7, nt = n >> 3;
            sB1[(((kt * 16 + nt) * 32) + ((n & 7) * 4 + (kk & 3))) * 2 + (kk >> 2)] = to_tf32(v);
        }
        __syncthreads();
#pragma unroll
        for (int kt = 0; kt < 8; ++kt) {
            float4 af = *(const float4*)&sA1[((wm * 8 + kt) * 32 + lane) * 4];
            unsigned a0 = __float_as_uint(af.x), a1 = __float_as_uint(af.y);
            unsigned a2 = __float_as_uint(af.z), a3 = __float_as_uint(af.w);
#pragma unroll
            for (int nt = 0; nt < 8; ++nt) {
                float2 bf = *(const float2*)&sB1[((kt * 16 + wn * 8 + nt) * 32 + lane) * 2];
                mma_tf32(acc[nt], a0, a1, a2, a3, __float_as_uint(bf.x), __float_as_uint(bf.y));
            }
        }
        __syncthreads();
    }

    // ---- relu(h1)+b1 -> layer-2 A fragments (tf32) ; stage W2 fragments ----
    float* sA2 = sm;            // 4 mt x 16 kt x 32 x 4 = 8192 floats
    float* sB2 = sm + 8192;     // 16 kt x 8 nt x 32 x 2 = 8192 floats
#pragma unroll
    for (int nt = 0; nt < 8; ++nt) {
        int col = wn * 64 + nt * 8 + 2 * tig;
        float bx = b1[col], by = b1[col + 1];
        float v00 = fmaxf(acc[nt][0] + bx, 0.f);
        float v01 = fmaxf(acc[nt][1] + by, 0.f);
        float v10 = fmaxf(acc[nt][2] + bx, 0.f);
        float v11 = fmaxf(acc[nt][3] + by, 0.f);
        // (row=wm*16+g / +8, k=col / col+1) -> fragment-major
        int kt0 = col >> 3, c0 = col & 7;
        int kt1 = (col + 1) >> 3, c1 = (col + 1) & 7;
        int rlo = g, rhi = g + 8;
        sA2[(((wm * 16 + kt0) * 32) + ((rlo & 7) * 4 + (c0 & 3))) * 4 + ((rlo >> 3) + 2 * (c0 >> 2))] = to_tf32(v00);
        sA2[(((wm * 16 + kt1) * 32) + ((rlo & 7) * 4 + (c1 & 3))) * 4 + ((rlo >> 3) + 2 * (c1 >> 2))] = to_tf32(v01);
        sA2[(((wm * 16 + kt0) * 32) + ((rhi & 7) * 4 + (c0 & 3))) * 4 + ((rhi >> 3) + 2 * (c0 >> 2))] = to_tf32(v10);
        sA2[(((wm * 16 + kt1) * 32) + ((rhi & 7) * 4 + (c1 & 3))) * 4 + ((rhi >> 3) + 2 * (c1 >> 2))] = to_tf32(v11);
    }
#pragma unroll
    for (int i = 0; i < 32; i++) {              // W2: 128 k x 64 n
        int idx = tid + i * 256;
        int k = idx >> 6, n = idx & 63;
        float v = W2[(size_t)k * 64 + n];
        int kt = k >> 3, kk = k & 7, nt = n >> 3;
        sB2[(((kt * 8 + nt) * 32) + ((n & 7) * 4 + (kk & 3))) * 2 + (kk >> 2)] = to_tf32(v);
    }
    __syncthreads();

    // ---- layer 2 mma ----
    float acc2[4][4] = {};
#pragma unroll
    for (int kt = 0; kt < 16; ++kt) {
        float4 af = *(const float4*)&sA2[((wm * 16 + kt) * 32 + lane) * 4];
        unsigned a0 = __float_as_uint(af.x), a1 = __float_as_uint(af.y);
        unsigned a2 = __float_as_uint(af.z), a3 = __float_as_uint(af.w);
#pragma unroll
        for (int j = 0; j < 4; ++j) {
            float2 bf = *(const float2*)&sB2[((kt * 8 + wn * 4 + j) * 32 + lane) * 2];
            mma_tf32(acc2[j], a0, a1, a2, a3, __float_as_uint(bf.x), __float_as_uint(bf.y));
        }
    }
    __syncthreads();

    // ---- relu(h2)+b2 -> sH2 ; layer 3 ----
    float* sH2 = sm;            // [64][68]
    float* sW3 = sm + 64 * 68;  // [64]
#pragma unroll
    for (int j = 0; j < 4; ++j) {
        int col = wn * 32 + j * 8 + 2 * tig;
        float bx = b2[col], by = b2[col + 1];
        int elo = wm * 16 + g, ehi = elo + 8;
        sH2[elo * 68 + col]     = fmaxf(acc2[j][0] + bx, 0.f);
        sH2[elo * 68 + col + 1] = fmaxf(acc2[j][1] + by, 0.f);
        sH2[ehi * 68 + col]     = fmaxf(acc2[j][2] + bx, 0.f);
        sH2[ehi * 68 + col + 1] = fmaxf(acc2[j][3] + by, 0.f);
    }
    if (tid < 64) sW3[tid] = W3[tid];
    __syncthreads();

    if (tid < 64) {
        float z = b3[0];
#pragma unroll
        for (int kk = 0; kk < 64; ++kk) z = fmaf(sH2[tid * 68 + kk], sW3[kk], z);
        out[e0 + tid] = 4.f / (1.f + expf(-z)) + 1.f;
    }
}

// ---------------- host launcher ----------------
extern "C" void kernel_launch(void* const* d_in, const int* in_sizes, int n_in,
                              void* d_out, int out_size) {
    const int* ei = (const int*)d_in[0];
    const float* x   = (const float*)d_in[2];
    const float* mem = (const float*)d_in[3];
    const float* Wq = (const float*)d_in[4];  const float* bq = (const float*)d_in[5];
    const float* Wk = (const float*)d_in[6];  const float* bk = (const float*)d_in[7];
    const float* Wv = (const float*)d_in[8];  const float* bv = (const float*)d_in[9];
    const float* Ws = (const float*)d_in[10]; const float* bs = (const float*)d_in[11];
    const float* W1 = (const float*)d_in[12]; const float* b1 = (const float*)d_in[13];
    const float* W2 = (const float*)d_in[14]; const float* b2 = (const float*)d_in[15];
    const float* W3 = (const float*)d_in[16]; const float* b3 = (const float*)d_in[17];
    float* out = (float*)d_out;

    // dynamic smem for edge MLP: 16384 floats = 64KB
    cudaFuncSetAttribute(edge_mlp_kernel, cudaFuncAttributeMaxDynamicSharedMemorySize, 65536);

    init_kernel<<<(N_NODES * 4 + 255) / 256, 256>>>();
    addh_kernel<<<(N_NODES * HID / 4 + 255) / 256, 256>>>((const float4*)x, (const float4*)mem);

    dim3 gg((N_NODES + 127) / 128, HD / 64);
    gemm_tf32_kernel<<<gg, 256>>>(Wq, bq, 0);
    gemm_tf32_kernel<<<gg, 256>>>(Wk, bk, 1);
    gemm_tf32_kernel<<<gg, 256>>>(Wv, bv, 2);
    gemm_tf32_kernel<<<gg, 256>>>(Ws, bs, 3);

    scores_kernel<<<(E_EDGES * 32 + 255) / 256, 256>>>(ei);
    expden_kernel<<<(E_EDGES * 4 + 255) / 256, 256>>>(ei);
    agg_kernel<<<(E_EDGES * 32 + 255) / 256, 256>>>(ei);

    edge_mlp_kernel<<<E_EDGES / 64, 256, 65536>>>(ei, W1, b1, W2, b2, W3, b3, out);
}

// round 7
// speedup vs baseline: 1.9849x; 1.9849x over previous
#include <cuda_runtime.h>
#include <cuda_bf16.h>
#include <math.h>
#include <stdint.h>

#define N_NODES 100000
#define E_EDGES 400000
#define HID 128
#define HD 256

// ---------------- scratch ----------------
__device__ float    g_h[(size_t)N_NODES * HID];
__device__ float    g_q[(size_t)N_NODES * HD];
__device__ float    g_k[(size_t)N_NODES * HD];
__device__ float    g_v[(size_t)N_NODES * HD];
__device__ float    g_out[(size_t)N_NODES * HD];
__device__ unsigned g_smax[(size_t)N_NODES * 4];
__device__ float    g_denom[(size_t)N_NODES * 4];
__device__ float    g_e[(size_t)E_EDGES * 4];
__device__ __align__(16) __nv_bfloat16 g_outb[(size_t)N_NODES * HD];
__device__ __align__(16) __nv_bfloat16 g_W1b[512 * 128];
__device__ __align__(16) __nv_bfloat16 g_W2b[128 * 64];

__device__ __forceinline__ unsigned fenc(float f) {
    unsigned b = __float_as_uint(f);
    return (b & 0x80000000u) ? ~b : (b | 0x80000000u);
}
__device__ __forceinline__ float fdec(unsigned u) {
    unsigned b = (u & 0x80000000u) ? (u & 0x7fffffffu) : ~u;
    return __uint_as_float(b);
}
__device__ __forceinline__ uint32_t smem_u32(const void* p) {
    uint32_t a;
    asm("{ .reg .u64 t; cvta.to.shared.u64 t, %1; cvt.u32.u64 %0, t; }" : "=r"(a) : "l"(p));
    return a;
}
__device__ __forceinline__ void ldsm_x4(uint32_t* r, uint32_t addr) {
    asm volatile("ldmatrix.sync.aligned.m8n8.x4.shared.b16 {%0,%1,%2,%3}, [%4];"
                 : "=r"(r[0]), "=r"(r[1]), "=r"(r[2]), "=r"(r[3]) : "r"(addr));
}
__device__ __forceinline__ void ldsm_x4_t(uint32_t* r, uint32_t addr) {
    asm volatile("ldmatrix.sync.aligned.m8n8.x4.trans.shared.b16 {%0,%1,%2,%3}, [%4];"
                 : "=r"(r[0]), "=r"(r[1]), "=r"(r[2]), "=r"(r[3]) : "r"(addr));
}
__device__ __forceinline__ void mma_bf16(float* d, const uint32_t* a, uint32_t b0, uint32_t b1) {
    asm volatile(
        "mma.sync.aligned.m16n8k16.row.col.f32.bf16.bf16.f32 "
        "{%0,%1,%2,%3}, {%4,%5,%6,%7}, {%8,%9}, {%0,%1,%2,%3};"
        : "+f"(d[0]), "+f"(d[1]), "+f"(d[2]), "+f"(d[3])
        : "r"(a[0]), "r"(a[1]), "r"(a[2]), "r"(a[3]), "r"(b0), "r"(b1));
}

// ---------------- small kernels ----------------
__global__ void init_kernel() {
    int i = blockIdx.x * blockDim.x + threadIdx.x;
    if (i < N_NODES * 4) { g_smax[i] = 0u; g_denom[i] = 0.f; }
}

__global__ void addh_kernel(const float4* __restrict__ x, const float4* __restrict__ mem) {
    int i = blockIdx.x * blockDim.x + threadIdx.x;
    if (i < N_NODES * HID / 4) {
        float4 a = x[i], b = mem[i];
        ((float4*)g_h)[i] = make_float4(a.x + b.x, a.y + b.y, a.z + b.z, a.w + b.w);
    }
}

__global__ void convert_w_kernel(const float* __restrict__ W1, const float* __restrict__ W2) {
    int i = blockIdx.x * blockDim.x + threadIdx.x;
    if (i < 32768) {
        float2 v = ((const float2*)W1)[i];
        ((__nv_bfloat162*)g_W1b)[i] = __float22bfloat162_rn(v);
    } else if (i < 32768 + 4096) {
        float2 v = ((const float2*)W2)[i - 32768];
        ((__nv_bfloat162*)g_W2b)[i - 32768] = __float22bfloat162_rn(v);
    }
}

__global__ void convert_out_kernel() {
    int i = blockIdx.x * blockDim.x + threadIdx.x;
    if (i < N_NODES * HD / 2) {
        float2 v = ((const float2*)g_out)[i];
        ((__nv_bfloat162*)g_outb)[i] = __float22bfloat162_rn(v);
    }
}

// ---------------- node GEMM (FFMA, known-good) ----------------
__global__ void gemm_bias_kernel(const float* __restrict__ W, const float* __restrict__ b, int sel) {
    __shared__ float sA[64][68];
    __shared__ float sB[64][64];
    float* C = (sel == 0) ? g_q : (sel == 1) ? g_k : (sel == 2) ? g_v : g_out;

    int row0 = blockIdx.x * 64;
    int col0 = blockIdx.y * 64;
    int tid = threadIdx.x;
    int tx = tid & 15, ty = tid >> 4;
    float acc[4][4] = {};

    for (int kt = 0; kt < 2; ++kt) {
        int k0 = kt * 64;
#pragma unroll
        for (int i = 0; i < 16; i++) {
            int idx = tid + i * 256;
            int r = idx >> 6, kk = idx & 63;
            int gr = row0 + r;
            float v = (gr < N_NODES) ? g_h[(size_t)gr * HID + k0 + kk] : 0.f;
            sA[kk][r] = v;
        }
#pragma unroll
        for (int i = 0; i < 16; i++) {
            int idx = tid + i * 256;
            int kk = idx >> 6, c = idx & 63;
            sB[kk][c] = W[(size_t)(k0 + kk) * HD + col0 + c];
        }
        __syncthreads();
#pragma unroll
        for (int kk = 0; kk < 64; ++kk) {
            float a[4], bb[4];
#pragma unroll
            for (int i = 0; i < 4; i++) a[i] = sA[kk][ty * 4 + i];
#pragma unroll
            for (int j = 0; j < 4; j++) bb[j] = sB[kk][tx * 4 + j];
#pragma unroll
            for (int i = 0; i < 4; i++)
#pragma unroll
                for (int j = 0; j < 4; j++) acc[i][j] = fmaf(a[i], bb[j], acc[i][j]);
        }
        __syncthreads();
    }
#pragma unroll
    for (int i = 0; i < 4; i++) {
        int gr = row0 + ty * 4 + i;
        if (gr < N_NODES) {
#pragma unroll
            for (int j = 0; j < 4; j++) {
                int gc = col0 + tx * 4 + j;
                C[(size_t)gr * HD + gc] = acc[i][j] + b[gc];
            }
        }
    }
}

// ---------------- attention ----------------
__global__ void scores_kernel(const int* __restrict__ ei) {
    int w = (blockIdx.x * blockDim.x + threadIdx.x) >> 5;
    int lane = threadIdx.x & 31;
    if (w >= E_EDGES) return;
    int src = ei[w];
    int dst = ei[E_EDGES + w];
    const float* qd = g_q + (size_t)dst * HD;
    const float* ks = g_k + (size_t)src * HD;
#pragma unroll
    for (int h = 0; h < 4; ++h) {
        float p = qd[h * 64 + lane] * ks[h * 64 + lane]
                + qd[h * 64 + 32 + lane] * ks[h * 64 + 32 + lane];
#pragma unroll
        for (int o = 16; o > 0; o >>= 1) p += __shfl_xor_sync(0xffffffffu, p, o);
        p *= 0.125f;
        if (lane == 0) {
            g_e[(size_t)w * 4 + h] = p;
            atomicMax(&g_smax[(size_t)dst * 4 + h], fenc(p));
        }
    }
}

__global__ void expden_kernel(const int* __restrict__ ei) {
    int i = blockIdx.x * blockDim.x + threadIdx.x;
    if (i >= E_EDGES * 4) return;
    int e = i >> 2, h = i & 3;
    int dst = ei[E_EDGES + e];
    float m = fdec(g_smax[(size_t)dst * 4 + h]);
    float ex = expf(g_e[i] - m);
    g_e[i] = ex;
    atomicAdd(&g_denom[(size_t)dst * 4 + h], ex);
}

__global__ void agg_kernel(const int* __restrict__ ei) {
    int w = (blockIdx.x * blockDim.x + threadIdx.x) >> 5;
    int lane = threadIdx.x & 31;
    if (w >= E_EDGES) return;
    int src = ei[w];
    int dst = ei[E_EDGES + w];
    const float* vs = g_v + (size_t)src * HD;
    float* od = g_out + (size_t)dst * HD;
#pragma unroll
    for (int h = 0; h < 4; ++h) {
        float alpha = g_e[(size_t)w * 4 + h] / (g_denom[(size_t)dst * 4 + h] + 1e-16f);
        atomicAdd(&od[h * 64 + lane], alpha * vs[h * 64 + lane]);
        atomicAdd(&od[h * 64 + 32 + lane], alpha * vs[h * 64 + 32 + lane]);
    }
}

// ---------------- bf16 mma.sync fused edge MLP ----------------
// 128 edges/block, 256 threads (8 warps: wm=wid&3 -> 32 edges, wn=wid>>2 -> half of N)
// L1: inter[128x512]b @ W1b[512x128] -> fp32 acc; relu(+b1) -> bf16 sA2
// L2: sA2[128x128]b @ W2b[128x64]  -> fp32 acc2; relu(+b2) . W3 -> z; sigmoid
__global__ void __launch_bounds__(256) edge_mlp_mma(
        const int* __restrict__ ei,
        const float* __restrict__ b1, const float* __restrict__ b2,
        const float* __restrict__ W3, const float* __restrict__ b3,
        float* __restrict__ out) {
    extern __shared__ __align__(16) char dsm[];
    __shared__ int s_src[128], s_dst[128];
    __shared__ float s_b1[128], s_b2[64], s_w3[64], sZ[128];

    const int tid = threadIdx.x;
    const int wid = tid >> 5, lane = tid & 31;
    const int g = lane >> 2, tig = lane & 3;
    const int wm = wid & 3, wn = wid >> 2;
    const int e0g = blockIdx.x * 128;

    const uint32_t Ab  = smem_u32(dsm);            // phase1 A: [128e][64k] bf16, 128B rows
    const uint32_t Bb  = Ab + 16384;               // phase1 B: [64k][128n] bf16, 256B rows
    const uint32_t A2b = Ab;                       // phase2 A: [128e][128k] bf16, 256B rows
    const uint32_t B2b = Ab + 32768;               // phase2 B: [128k][64n] bf16, 128B rows

    if (tid < 128) {
        s_src[tid] = ei[e0g + tid];
        s_dst[tid] = ei[E_EDGES + e0g + tid];
        s_b1[tid] = b1[tid];
        sZ[tid] = 0.f;
    } else {
        int t = tid - 128;
        if (t < 64) { s_b2[t] = b2[t]; s_w3[t] = W3[t]; }
    }

    // stage B2 (W2 bf16) once: region disjoint from phase-1 tiles
    {
        int k = tid >> 1, half = tid & 1;
#pragma unroll
        for (int j = 0; j < 4; ++j) {
            int n = half * 32 + j * 8;
            uint4 v = *(const uint4*)(g_W2b + k * 64 + n);
            int c = (half * 4 + j) ^ (k & 7);
            *(uint4*)(dsm + (B2b - Ab) + k * 128 + c * 16) = v;
        }
    }
    __syncthreads();

    // ---- layer 1: K = 512 in 8 chunks of 64 ----
    float acc[2][8][4] = {};
    for (int ch = 0; ch < 8; ++ch) {
        const int k0g = ch * 64;
        // A: [128e][64k] gather from g_outb
        {
            int e = tid >> 1, half = tid & 1;
            int node = (k0g < HD) ? s_src[e] : s_dst[e];
            int colbase = (k0g & (HD - 1)) + half * 32;
            const __nv_bfloat16* rowp = g_outb + (size_t)node * HD + colbase;
#pragma unroll
            for (int j = 0; j < 4; ++j) {
                uint4 v = *(const uint4*)(rowp + j * 8);
                int c = (half * 4 + j) ^ (e & 7);
                *(uint4*)(dsm + e * 128 + c * 16) = v;
            }
        }
        // B: [64k][128n] from g_W1b
        {
            int k = tid >> 2, q = tid & 3;
            const __nv_bfloat16* wp = g_W1b + (size_t)(k0g + k) * 128 + q * 32;
#pragma unroll
            for (int j = 0; j < 4; ++j) {
                uint4 v = *(const uint4*)(wp + j * 8);
                int c = (q * 4 + j) ^ (k & 7);
                *(uint4*)(dsm + 16384 + k * 256 + c * 16) = v;
            }
        }
        __syncthreads();
#pragma unroll
        for (int ks = 0; ks < 4; ++ks) {
            const int k0 = ks * 16;
            uint32_t a[2][4];
#pragma unroll
            for (int mt = 0; mt < 2; ++mt) {
                int e = wm * 32 + mt * 16 + (lane & 15);
                int k = k0 + (lane >> 4) * 8;
                int c = (k >> 3) ^ (e & 7);
                ldsm_x4(a[mt], Ab + e * 128 + c * 16);
            }
#pragma unroll
            for (int ntp = 0; ntp < 4; ++ntp) {
                int k = k0 + (lane & 15);
                int n = wn * 64 + ntp * 16 + (lane >> 4) * 8;
                int c = (n >> 3) ^ (k & 7);
                uint32_t b[4];
                ldsm_x4_t(b, Bb + k * 256 + c * 16);
#pragma unroll
                for (int mt = 0; mt < 2; ++mt) {
                    mma_bf16(acc[mt][ntp * 2],     a[mt], b[0], b[1]);
                    mma_bf16(acc[mt][ntp * 2 + 1], a[mt], b[2], b[3]);
                }
            }
        }
        __syncthreads();
    }

    // ---- epilogue L1: relu(acc + b1) -> bf16 sA2 [128e][128k] ----
#pragma unroll
    for (int mt = 0; mt < 2; ++mt) {
#pragma unroll
        for (int nt = 0; nt < 8; ++nt) {
            int col = wn * 64 + nt * 8 + tig * 2;
            float bx = s_b1[col], by = s_b1[col + 1];
            int elo = wm * 32 + mt * 16 + g, ehi = elo + 8;
            __nv_bfloat162 lo, hi;
            lo.x = __float2bfloat16(fmaxf(acc[mt][nt][0] + bx, 0.f));
            lo.y = __float2bfloat16(fmaxf(acc[mt][nt][1] + by, 0.f));
            hi.x = __float2bfloat16(fmaxf(acc[mt][nt][2] + bx, 0.f));
            hi.y = __float2bfloat16(fmaxf(acc[mt][nt][3] + by, 0.f));
            int c = (col >> 3);
            int clo = (c ^ (elo & 7)) * 16 + (col & 7) * 2;
            int chi = (c ^ (ehi & 7)) * 16 + (col & 7) * 2;
            *(__nv_bfloat162*)(dsm + elo * 256 + clo) = lo;
            *(__nv_bfloat162*)(dsm + ehi * 256 + chi) = hi;
        }
    }
    __syncthreads();

    // ---- layer 2: [128x128] @ [128x64] ----
    float acc2[2][4][4] = {};
#pragma unroll
    for (int ks = 0; ks < 8; ++ks) {
        const int k0 = ks * 16;
        uint32_t a[2][4];
#pragma unroll
        for (int mt = 0; mt < 2; ++mt) {
            int e = wm * 32 + mt * 16 + (lane & 15);
            int k = k0 + (lane >> 4) * 8;
            int c = (k >> 3) ^ (e & 7);
            ldsm_x4(a[mt], A2b + e * 256 + c * 16);
        }
#pragma unroll
        for (int ntp = 0; ntp < 2; ++ntp) {
            int k = k0 + (lane & 15);
            int n = wn * 32 + ntp * 16 + (lane >> 4) * 8;
            int c = (n >> 3) ^ (k & 7);
            uint32_t b[4];
            ldsm_x4_t(b, B2b + k * 128 + c * 16);
#pragma unroll
            for (int mt = 0; mt < 2; ++mt) {
                mma_bf16(acc2[mt][ntp * 2],     a[mt], b[0], b[1]);
                mma_bf16(acc2[mt][ntp * 2 + 1], a[mt], b[2], b[3]);
            }
        }
    }

    // ---- epilogue L2: relu(+b2) . w3 -> sZ ----
#pragma unroll
    for (int mt = 0; mt < 2; ++mt) {
        float zlo = 0.f, zhi = 0.f;
#pragma unroll
        for (int nt = 0; nt < 4; ++nt) {
            int col = wn * 32 + nt * 8 + tig * 2;
            float bx = s_b2[col], by = s_b2[col + 1];
            float wx = s_w3[col], wy = s_w3[col + 1];
            zlo += fmaxf(acc2[mt][nt][0] + bx, 0.f) * wx + fmaxf(acc2[mt][nt][1] + by, 0.f) * wy;
            zhi += fmaxf(acc2[mt][nt][2] + bx, 0.f) * wx + fmaxf(acc2[mt][nt][3] + by, 0.f) * wy;
        }
        zlo += __shfl_xor_sync(0xffffffffu, zlo, 1);
        zlo += __shfl_xor_sync(0xffffffffu, zlo, 2);
        zhi += __shfl_xor_sync(0xffffffffu, zhi, 1);
        zhi += __shfl_xor_sync(0xffffffffu, zhi, 2);
        if (tig == 0) {
            atomicAdd(&sZ[wm * 32 + mt * 16 + g], zlo);
            atomicAdd(&sZ[wm * 32 + mt * 16 + g + 8], zhi);
        }
    }
    __syncthreads();

    if (tid < 128) {
        float z = sZ[tid] + b3[0];
        out[e0g + tid] = 4.f / (1.f + expf(-z)) + 1.f;
    }
}

// ---------------- host launcher ----------------
extern "C" void kernel_launch(void* const* d_in, const int* in_sizes, int n_in,
                              void* d_out, int out_size) {
    const int* ei = (const int*)d_in[0];
    const float* x   = (const float*)d_in[2];
    const float* mem = (const float*)d_in[3];
    const float* Wq = (const float*)d_in[4];  const float* bq = (const float*)d_in[5];
    const float* Wk = (const float*)d_in[6];  const float* bk = (const float*)d_in[7];
    const float* Wv = (const float*)d_in[8];  const float* bv = (const float*)d_in[9];
    const float* Ws = (const float*)d_in[10]; const float* bs = (const float*)d_in[11];
    const float* W1 = (const float*)d_in[12]; const float* b1 = (const float*)d_in[13];
    const float* W2 = (const float*)d_in[14]; const float* b2 = (const float*)d_in[15];
    const float* W3 = (const float*)d_in[16]; const float* b3 = (const float*)d_in[17];
    float* out = (float*)d_out;

    cudaFuncSetAttribute(edge_mlp_mma, cudaFuncAttributeMaxDynamicSharedMemorySize, 49152);

    init_kernel<<<(N_NODES * 4 + 255) / 256, 256>>>();
    addh_kernel<<<(N_NODES * HID / 4 + 255) / 256, 256>>>((const float4*)x, (const float4*)mem);
    convert_w_kernel<<<(36864 + 255) / 256, 256>>>(W1, W2);

    dim3 gg((N_NODES + 63) / 64, HD / 64);
    gemm_bias_kernel<<<gg, 256>>>(Wq, bq, 0);
    gemm_bias_kernel<<<gg, 256>>>(Wk, bk, 1);
    gemm_bias_kernel<<<gg, 256>>>(Wv, bv, 2);
    gemm_bias_kernel<<<gg, 256>>>(Ws, bs, 3);

    scores_kernel<<<(E_EDGES * 32 + 255) / 256, 256>>>(ei);
    expden_kernel<<<(E_EDGES * 4 + 255) / 256, 256>>>(ei);
    agg_kernel<<<(E_EDGES * 32 + 255) / 256, 256>>>(ei);

    convert_out_kernel<<<(N_NODES * HD / 2 + 255) / 256, 256>>>();
    edge_mlp_mma<<<E_EDGES / 128, 256, 49152>>>(ei, b1, b2, W3, b3, out);
}